// round 11
// baseline (speedup 1.0000x reference)
#include <cuda_runtime.h>
#include <stdint.h>

#define KEHALF   7.199822675975274f
#define CUTOFF   10.0f
#define L2E      1.4426950408889634f
#define NTHREADS 1024
#define CAP_E    (1 << 22)          // 4.19M edges of scratch

// per-edge byte: (Zi-1)+(Zj-1), built by kernel A
__device__ __align__(16) uint8_t g_wsum[CAP_E];

__device__ __forceinline__ float softplus_f(float x) {
    return (x > 20.0f) ? x : log1pf(__expf(x));
}

// ---------------- Kernel A: build table in smem + gather pass --------------
__global__ __launch_bounds__(NTHREADS, 1) void k_gather(
    const float* __restrict__ Z,
    const int* __restrict__ ii, const int* __restrict__ jj,
    int N, int E, float* __restrict__ y, int M)
{
    extern __shared__ __align__(16) uint8_t ztab[];
    int tid = threadIdx.x;

    // zero output (block 0)
    if (blockIdx.x == 0)
        for (int b = tid; b < M; b += blockDim.x) y[b] = 0.0f;

    // Build byte table straight from Z (coalesced float4; L2-broadcast)
    {
        int n4 = N >> 2;
        const float4* z4 = (const float4*)Z;
        for (int k = tid; k < n4; k += blockDim.x) {
            float4 v = __ldg(z4 + k);
            uint32_t w =  (uint32_t)((int)(v.x + 0.5f) - 1)
                       | ((uint32_t)((int)(v.y + 0.5f) - 1) << 8)
                       | ((uint32_t)((int)(v.z + 0.5f) - 1) << 16)
                       | ((uint32_t)((int)(v.w + 0.5f) - 1) << 24);
            *(uint32_t*)(ztab + 4 * k) = w;
        }
        for (int k = (n4 << 2) + tid; k < N; k += blockDim.x)
            ztab[k] = (uint8_t)((int)(__ldg(Z + k) + 0.5f) - 1);
    }
    __syncthreads();

    int E8     = E & ~7;
    int Ecap   = (E8 < CAP_E) ? E8 : CAP_E;
    int stride = gridDim.x * blockDim.x * 8;

    for (int e = (blockIdx.x * blockDim.x + tid) * 8; e < Ecap; e += stride) {
        int4 iva = __ldcs((const int4*)(ii + e));
        int4 ivb = __ldcs((const int4*)(ii + e + 4));
        int4 jva = __ldcs((const int4*)(jj + e));
        int4 jvb = __ldcs((const int4*)(jj + e + 4));

        uint32_t w0 =  (uint32_t)(ztab[iva.x] + ztab[jva.x])
                    | ((uint32_t)(ztab[iva.y] + ztab[jva.y]) << 8)
                    | ((uint32_t)(ztab[iva.z] + ztab[jva.z]) << 16)
                    | ((uint32_t)(ztab[iva.w] + ztab[jva.w]) << 24);
        uint32_t w1 =  (uint32_t)(ztab[ivb.x] + ztab[jvb.x])
                    | ((uint32_t)(ztab[ivb.y] + ztab[jvb.y]) << 8)
                    | ((uint32_t)(ztab[ivb.z] + ztab[jvb.z]) << 16)
                    | ((uint32_t)(ztab[ivb.w] + ztab[jvb.w]) << 24);

        *(uint2*)(g_wsum + e) = make_uint2(w0, w1);
    }

    // tail bytes (E8..min(E,CAP))
    if (blockIdx.x == 0)
        for (int e = E8 + tid; e < E && e < CAP_E; e += blockDim.x)
            g_wsum[e] = (uint8_t)(ztab[ii[e]] + ztab[jj[e]]);
}

// ---------------- Kernel B: stream + test + sparse exact energy ------------
// cf layout: [0..3]=b, [4..7]=c, [8]=thr, [9]=wthr2, [10]=spw
__device__ __forceinline__ void survivor_edge(
    float s, int e,
    const float* __restrict__ Z,
    const int* __restrict__ ii, const int* __restrict__ jj,
    const int* __restrict__ im,
    const float* __restrict__ cf, float* bins)
{
    int   i  = __ldg(ii + e);
    int   j  = __ldg(jj + e);
    float Zi = __ldg(Z + i);
    float Zj = __ldg(Z + j);
    float spw = cf[10];
    float zsum = exp2f(spw * log2f(Zi)) + exp2f(spw * log2f(Zj));  // Z >= 1
    float rs = rsqrtf(s);
    float d  = s * rs;
    float t  = zsum * d;
    if (t < cf[8] && d < CUTOFF) {   // exact test (beyond thr: exp2 -> 0.0f)
        float f = cf[4] * exp2f(-cf[0] * t) + cf[5] * exp2f(-cf[1] * t)
                + cf[6] * exp2f(-cf[2] * t) + cf[7] * exp2f(-cf[3] * t);
        float u  = d * (1.0f / CUTOFF);
        float u3 = u * u * u;
        float p  = fmaf(-6.0f, u, 15.0f);
        p        = fmaf(p, u, -10.0f);
        float fc = fmaf(u3, p, 1.0f);
        float ee = KEHALF * f * fc * Zi * Zj * rs;
        if (ee != 0.0f) atomicAdd(&bins[__ldg(im + i)], ee);
    }
}

__global__ __launch_bounds__(NTHREADS, 2) void k_energy(
    const float* __restrict__ r,
    const float* __restrict__ Z,
    const int*   __restrict__ ii,
    const int*   __restrict__ jj,
    const int*   __restrict__ im,
    const float* __restrict__ adiv,
    const float* __restrict__ apow,
    const float* __restrict__ av,
    const float* __restrict__ cv,
    int E, float* __restrict__ y, int M)
{
    extern __shared__ __align__(16) char smem_raw[];
    float* bins = (float*)smem_raw;      // M floats (4KB)
    float* cf   = bins + M;              // 16 floats

    int tid = threadIdx.x;

    for (int b = tid; b < M; b += blockDim.x) bins[b] = 0.0f;

    if (tid == 0) {
        float sp_adiv = softplus_f(adiv[0]);
        float a0 = softplus_f(av[0]), a1 = softplus_f(av[1]);
        float a2 = softplus_f(av[2]), a3 = softplus_f(av[3]);
        float c0 = softplus_f(cv[0]), c1 = softplus_f(cv[1]);
        float c2 = softplus_f(cv[2]), c3 = softplus_f(cv[3]);
        float cinv = 1.0f / (fabsf(c0) + fabsf(c1) + fabsf(c2) + fabsf(c3));
        float b0 = a0 * sp_adiv * L2E, b1 = a1 * sp_adiv * L2E;
        float b2 = a2 * sp_adiv * L2E, b3 = a3 * sp_adiv * L2E;
        cf[0] = b0; cf[1] = b1; cf[2] = b2; cf[3] = b3;
        cf[4] = c0 * cinv; cf[5] = c1 * cinv; cf[6] = c2 * cinv; cf[7] = c3 * cinv;
        float bmin = fminf(fminf(b0, b1), fminf(b2, b3));
        float thr  = 151.0f / bmin;  // t >= thr => every exp2 term is exactly 0.0f
        cf[8] = thr;
        float spw = softplus_f(apow[0]);
        // Conservative pre-test threshold valid only when z >= Z (p >= 1)
        cf[9]  = (spw >= 1.0f) ? thr * thr : 3.0e38f;
        cf[10] = spw;
    }
    __syncthreads();

    float wthr2 = cf[9];

    int E4     = E & ~3;
    int Ecap   = (E4 < CAP_E) ? E4 : (CAP_E & ~3);
    int stride = gridDim.x * blockDim.x * 4;
    const float4* rv = (const float4*)r;

    for (int e = (blockIdx.x * blockDim.x + tid) * 4; e < Ecap; e += stride) {
        int fi = (e >> 2) * 3;
        float4 p0 = __ldcs(rv + fi + 0);
        float4 p1 = __ldcs(rv + fi + 1);
        float4 p2 = __ldcs(rv + fi + 2);
        uint32_t w4 = __ldcs((const uint32_t*)(g_wsum + e));

        float fx[12] = {p0.x, p0.y, p0.z, p0.w,
                        p1.x, p1.y, p1.z, p1.w,
                        p2.x, p2.y, p2.z, p2.w};

        #pragma unroll
        for (int k = 0; k < 4; k++) {
            float rx = fx[3 * k], ry = fx[3 * k + 1], rz = fx[3 * k + 2];
            float s  = fmaf(rx, rx, fmaf(ry, ry, rz * rz));     // d^2
            float wf = (float)((w4 >> (8 * k)) & 255u) + 2.0f;  // Zi+Zj <= zsum
            // survivor => (Zi+Zj)*d < thr  =>  wf^2*s < thr^2 ; d<10 => s<100
            if (wf * wf * s < wthr2 && s < CUTOFF * CUTOFF)     // ~1% taken
                survivor_edge(s, e + k, Z, ii, jj, im, cf, bins);
        }
    }

    // tail: E%4 plus anything beyond scratch capacity -> exact path
    if (blockIdx.x < 2) {
        for (int e = Ecap + blockIdx.x * blockDim.x + tid; e < E;
             e += 2 * blockDim.x) {
            float rx = r[3 * e], ry = r[3 * e + 1], rz = r[3 * e + 2];
            float s  = fmaf(rx, rx, fmaf(ry, ry, rz * rz));
            survivor_edge(s, e, Z, ii, jj, im, cf, bins);
        }
    }

    __syncthreads();
    for (int b = tid; b < M; b += blockDim.x) {
        float v = bins[b];
        if (v != 0.0f) atomicAdd(&y[b], v);
    }
}

extern "C" void kernel_launch(void* const* d_in, const int* in_sizes, int n_in,
                              void* d_out, int out_size) {
    const float* Z    = (const float*)d_in[0];
    const float* r    = (const float*)d_in[1];
    const int*   ii   = (const int*)  d_in[2];
    const int*   jj   = (const int*)  d_in[3];
    const int*   im   = (const int*)  d_in[4];
    const float* adiv = (const float*)d_in[5];
    const float* apow = (const float*)d_in[6];
    const float* av   = (const float*)d_in[7];
    const float* cv   = (const float*)d_in[8];

    int N = in_sizes[0];
    int E = in_sizes[2];
    int M = out_size;
    float* y = (float*)d_out;

    int sm_count = 148;
    cudaDeviceGetAttribute(&sm_count, cudaDevAttrMultiProcessorCount, 0);

    // Kernel A: table build + gather (smem = ztab bytes)
    size_t smem_a = (size_t)N + 16;
    cudaFuncSetAttribute(k_gather,
                         cudaFuncAttributeMaxDynamicSharedMemorySize, (int)smem_a);
    k_gather<<<sm_count, NTHREADS, smem_a>>>(Z, ii, jj, N, E, y, M);

    // Kernel B: stream + sparse exact energy (smem = bins + cf ~ 4.1KB)
    size_t smem_b = (size_t)M * 4 + 16 * 4;
    cudaFuncSetAttribute(k_energy,
                         cudaFuncAttributeMaxDynamicSharedMemorySize, (int)smem_b);
    k_energy<<<2 * sm_count, NTHREADS, smem_b>>>(
        r, Z, ii, jj, im, adiv, apow, av, cv, E, y, M);
}

// round 12
// speedup vs baseline: 1.2243x; 1.2243x over previous
#include <cuda_runtime.h>
#include <stdint.h>

#define KEHALF   7.199822675975274f
#define CUTOFF   10.0f
#define L2E      1.4426950408889634f
#define ZMAX     94
#define LUT_REP  32
#define NTHREADS 1024
#define NWARP    (NTHREADS / 32)
#define SCAP     64                 // per-warp survivor stack capacity

// per-atom z-index bytes (Z-1), built by prep kernel
__device__ __align__(16) uint8_t g_ztab[131072];

__device__ __forceinline__ float softplus_f(float x) {
    return (x > 20.0f) ? x : log1pf(__expf(x));
}

__global__ void k_prep(const float* __restrict__ Z, int N,
                       float* __restrict__ y, int M) {
    int i = blockIdx.x * blockDim.x + threadIdx.x;
    if (i < M) y[i] = 0.0f;
    if (i < N && i < 131072) g_ztab[i] = (uint8_t)((int)(Z[i] + 0.5f) - 1);
}

// Exact evaluation of a batch of queued survivor edges, one per lane.
// cf: [0..3]=b, [4..7]=c, [8]=thr
__device__ __noinline__ void drain_warp(
    int cnt, const int* __restrict__ wse, const float* __restrict__ wss,
    const int* __restrict__ ii, const int* __restrict__ jj,
    const int* __restrict__ im,
    const uint8_t* __restrict__ ztab, const float* __restrict__ zlut,
    const float* __restrict__ cf, float* __restrict__ bins, int lane)
{
    __syncwarp();
    float thr = cf[8];
    for (int base = 0; base < cnt; base += 32) {
        int  idx = base + lane;
        bool act = idx < cnt;
        int   e = act ? wse[idx] : 0;
        float s = act ? wss[idx] : 1.0f;
        int i = 0, j = 0;
        if (act) { i = __ldg(ii + e); j = __ldg(jj + e); }   // parallel gathers
        int zi = ztab[i], zj = ztab[j];
        float zsum = zlut[zi * LUT_REP + lane] + zlut[zj * LUT_REP + lane];
        float rs = rsqrtf(s);
        float d  = s * rs;
        float t  = zsum * d;
        if (act && t < thr && d < CUTOFF) {   // exact test (beyond thr: exp2->0)
            float f = cf[4] * exp2f(-cf[0] * t) + cf[5] * exp2f(-cf[1] * t)
                    + cf[6] * exp2f(-cf[2] * t) + cf[7] * exp2f(-cf[3] * t);
            float u  = d * (1.0f / CUTOFF);
            float u3 = u * u * u;
            float p  = fmaf(-6.0f, u, 15.0f);
            p        = fmaf(p, u, -10.0f);
            float fc = fmaf(u3, p, 1.0f);
            float Zi = (float)(zi + 1), Zj = (float)(zj + 1);
            float ee = KEHALF * f * fc * Zi * Zj * rs;
            if (ee != 0.0f) atomicAdd(&bins[__ldg(im + i)], ee);
        }
    }
    __syncwarp();
}

__global__ __launch_bounds__(NTHREADS, 1) void k_edge(
    const float* __restrict__ r,
    const int*   __restrict__ ii,
    const int*   __restrict__ jj,
    const int*   __restrict__ im,
    const float* __restrict__ adiv,
    const float* __restrict__ apow,
    const float* __restrict__ av,
    const float* __restrict__ cv,
    int N, int E, float* __restrict__ y, int M)
{
    extern __shared__ __align__(16) char smem_raw[];
    float*   bins = (float*)smem_raw;                    // M floats
    float*   cf   = bins + M;                            // 16 floats
    float*   zlut = cf + 16;                             // 94*32 floats
    int*     se   = (int*)(zlut + ZMAX * LUT_REP);       // NWARP*SCAP ints
    float*   ss   = (float*)(se + NWARP * SCAP);         // NWARP*SCAP floats
    uint8_t* ztab = (uint8_t*)(((uintptr_t)(ss + NWARP * SCAP) + 15)
                               & ~(uintptr_t)15);        // N bytes

    int tid  = threadIdx.x;
    int wid  = tid >> 5;
    int lane = tid & 31;
    int* wse = se + wid * SCAP;
    float* wss = ss + wid * SCAP;

    for (int b = tid; b < M; b += blockDim.x) bins[b] = 0.0f;

    if (tid == 0) {
        float sp_adiv = softplus_f(adiv[0]);
        float a0 = softplus_f(av[0]), a1 = softplus_f(av[1]);
        float a2 = softplus_f(av[2]), a3 = softplus_f(av[3]);
        float c0 = softplus_f(cv[0]), c1 = softplus_f(cv[1]);
        float c2 = softplus_f(cv[2]), c3 = softplus_f(cv[3]);
        float cinv = 1.0f / (fabsf(c0) + fabsf(c1) + fabsf(c2) + fabsf(c3));
        float b0 = a0 * sp_adiv * L2E, b1 = a1 * sp_adiv * L2E;
        float b2 = a2 * sp_adiv * L2E, b3 = a3 * sp_adiv * L2E;
        cf[0] = b0; cf[1] = b1; cf[2] = b2; cf[3] = b3;
        cf[4] = c0 * cinv; cf[5] = c1 * cinv; cf[6] = c2 * cinv; cf[7] = c3 * cinv;
        float bmin = fminf(fminf(b0, b1), fminf(b2, b3));
        float thr  = 151.0f / bmin;  // t >= thr => every exp2 term is exactly 0.0f
        cf[8] = thr;
        float spw = softplus_f(apow[0]);
        // Conservative pre-test threshold valid only when z >= Z (p >= 1)
        cf[9] = (spw >= 1.0f) ? thr * thr : 3.0e38f;
    }

    {   // bank-replicated z-LUT: zlut[zi*32 + lane] -> bank == lane
        float spw = softplus_f(apow[0]);
        for (int k = tid; k < ZMAX * LUT_REP; k += blockDim.x) {
            int zi = k / LUT_REP;
            zlut[k] = exp2f(spw * log2f((float)(zi + 1)));
        }
    }

    {   // stage byte table into smem
        const int4* src = (const int4*)g_ztab;
        int4*       dst = (int4*)ztab;
        int n16 = N >> 4;
        for (int k = tid; k < n16; k += blockDim.x) dst[k] = src[k];
        for (int k = (n16 << 4) + tid; k < N; k += blockDim.x) ztab[k] = g_ztab[k];
    }

    __syncthreads();

    float wthr2 = cf[9];
    unsigned lm  = (1u << lane) - 1u;

    // warp-uniform 256-edge blocks: every lane processes 8 consecutive edges
    int gw = blockIdx.x * NWARP + wid;
    int nw = gridDim.x * NWARP;
    int NB = E >> 8;
    int cnt = 0;

    for (int b = gw; b < NB; b += nw) {
        int e0 = (b << 8) + lane * 8;

        const float4* rq = (const float4*)r + ((b << 6) + lane * 2) * 3;
        float4 q0 = rq[0], q1 = rq[1], q2 = rq[2];
        float4 q3 = rq[3], q4 = rq[4], q5 = rq[5];
        int4 iva = *(const int4*)(ii + e0);
        int4 ivb = *(const int4*)(ii + e0 + 4);
        int4 jva = *(const int4*)(jj + e0);
        int4 jvb = *(const int4*)(jj + e0 + 4);

        int zs[8];
        zs[0] = ztab[iva.x] + ztab[jva.x];
        zs[1] = ztab[iva.y] + ztab[jva.y];
        zs[2] = ztab[iva.z] + ztab[jva.z];
        zs[3] = ztab[iva.w] + ztab[jva.w];
        zs[4] = ztab[ivb.x] + ztab[jvb.x];
        zs[5] = ztab[ivb.y] + ztab[jvb.y];
        zs[6] = ztab[ivb.z] + ztab[jvb.z];
        zs[7] = ztab[ivb.w] + ztab[jvb.w];

        float fx[24] = {q0.x, q0.y, q0.z, q0.w, q1.x, q1.y, q1.z, q1.w,
                        q2.x, q2.y, q2.z, q2.w, q3.x, q3.y, q3.z, q3.w,
                        q4.x, q4.y, q4.z, q4.w, q5.x, q5.y, q5.z, q5.w};

        #pragma unroll
        for (int k = 0; k < 8; k++) {
            float rx = fx[3 * k], ry = fx[3 * k + 1], rz = fx[3 * k + 2];
            float s  = fmaf(rx, rx, fmaf(ry, ry, rz * rz));     // d^2
            float wf = (float)(zs[k] + 2);                      // <= zsum exact
            bool pass = (wf * wf * s < wthr2) && (s < CUTOFF * CUTOFF);
            unsigned mask = __ballot_sync(0xffffffffu, pass);
            if (mask) {                                         // rare (~1%)
                int n = __popc(mask);
                if (cnt + n > SCAP) {
                    drain_warp(cnt, wse, wss, ii, jj, im, ztab, zlut,
                               cf, bins, lane);
                    cnt = 0;
                }
                if (pass) {
                    int pos = cnt + __popc(mask & lm);
                    wse[pos] = e0 + k;
                    wss[pos] = s;
                }
                cnt += n;
            }
        }
    }

    if (cnt > 0)
        drain_warp(cnt, wse, wss, ii, jj, im, ztab, zlut, cf, bins, lane);

    // tail edges (E % 256): block 0, warp 0, exact path without stack
    if (blockIdx.x == 0 && wid == 0) {
        float thr = cf[8];
        for (int e = (NB << 8) + lane; e < E; e += 32) {
            int i = ii[e], j = jj[e];
            int zi = ztab[i], zj = ztab[j];
            float zsum = zlut[zi * LUT_REP + lane] + zlut[zj * LUT_REP + lane];
            float rx = r[3 * e], ry = r[3 * e + 1], rz = r[3 * e + 2];
            float s  = fmaf(rx, rx, fmaf(ry, ry, rz * rz));
            float rs = rsqrtf(s);
            float d  = s * rs;
            float t  = zsum * d;
            if (t < thr && d < CUTOFF) {
                float f = cf[4] * exp2f(-cf[0] * t) + cf[5] * exp2f(-cf[1] * t)
                        + cf[6] * exp2f(-cf[2] * t) + cf[7] * exp2f(-cf[3] * t);
                float u  = d * (1.0f / CUTOFF);
                float u3 = u * u * u;
                float p  = fmaf(-6.0f, u, 15.0f);
                p        = fmaf(p, u, -10.0f);
                float fc = fmaf(u3, p, 1.0f);
                float Zi = (float)(zi + 1), Zj = (float)(zj + 1);
                float ee = KEHALF * f * fc * Zi * Zj * rs;
                if (ee != 0.0f) atomicAdd(&bins[im[i]], ee);
            }
        }
    }

    __syncthreads();
    for (int b = tid; b < M; b += blockDim.x) {
        float v = bins[b];
        if (v != 0.0f) atomicAdd(&y[b], v);
    }
}

extern "C" void kernel_launch(void* const* d_in, const int* in_sizes, int n_in,
                              void* d_out, int out_size) {
    const float* Z    = (const float*)d_in[0];
    const float* r    = (const float*)d_in[1];
    const int*   ii   = (const int*)  d_in[2];
    const int*   jj   = (const int*)  d_in[3];
    const int*   im   = (const int*)  d_in[4];
    const float* adiv = (const float*)d_in[5];
    const float* apow = (const float*)d_in[6];
    const float* av   = (const float*)d_in[7];
    const float* cv   = (const float*)d_in[8];

    int N = in_sizes[0];
    int E = in_sizes[2];
    int M = out_size;
    float* y = (float*)d_out;

    int prep_n = (N > M ? N : M);
    k_prep<<<(prep_n + 255) / 256, 256>>>(Z, N, y, M);

    int sm_count = 148;
    cudaDeviceGetAttribute(&sm_count, cudaDevAttrMultiProcessorCount, 0);

    size_t smem = (size_t)M * 4 + 16 * 4
                + (size_t)ZMAX * LUT_REP * 4
                + (size_t)NWARP * SCAP * 8
                + 32 + (size_t)N;
    cudaFuncSetAttribute(k_edge,
                         cudaFuncAttributeMaxDynamicSharedMemorySize, (int)smem);
    k_edge<<<sm_count, NTHREADS, smem>>>(
        r, ii, jj, im, adiv, apow, av, cv, N, E, y, M);
}